// round 11
// baseline (speedup 1.0000x reference)
#include <cuda_runtime.h>
#include <cuda_fp16.h>

#define OUT_COLS 256
#define SLICE 128
#define NSLICES (OUT_COLS / SLICE)          // 2
#define BLOCK_THREADS 1024
#define NWARPS (BLOCK_THREADS / 32)
#define ROW_BLOCKS 76                       // 2 slices * 76 = 152 CTAs = 1 wave

typedef unsigned long long ull;

// scratch (static __device__ globals: no allocations allowed)
__device__ int2   g_pairs[1 << 20];          // (col, val_bits) per nnz
__device__ int    g_row_off[(1 << 16) + 2];  // N+1 row segment offsets
__device__ __half g_whalf[1 << 18];          // fp16 copy of W
__device__ int    g_ctr[2];                  // work-queue counters (per slice)

// Prep, 4 nnz per thread: vector loads + 4 independent ftab gathers (MLP=4).
__global__ void prep_kernel(const int* __restrict__ bidx,
                            const int* __restrict__ aidx,
                            const float* __restrict__ vals,
                            const int* __restrict__ ftab,
                            int nnz, int N) {
    int t = blockIdx.x * blockDim.x + threadIdx.x;
    if (t == 0) { g_ctr[0] = 0; g_ctr[1] = 0; }
    int k4 = t * 4;
    if (k4 >= nnz) return;

    if (k4 + 3 < nnz) {
        int4   a = *(const int4*)(aidx + k4);
        float4 v = *(const float4*)(vals + k4);
        int4   b = *(const int4*)(bidx + k4);
        int c0 = ftab[a.x], c1 = ftab[a.y], c2 = ftab[a.z], c3 = ftab[a.w];
        int4* dst = (int4*)(g_pairs + k4);
        dst[0] = make_int4(c0, __float_as_int(v.x), c1, __float_as_int(v.y));
        dst[1] = make_int4(c2, __float_as_int(v.z), c3, __float_as_int(v.w));
        int prev = (k4 == 0) ? -1 : bidx[k4 - 1];
        int bb[4] = {b.x, b.y, b.z, b.w};
#pragma unroll
        for (int i = 0; i < 4; ++i) {
            for (int r = prev + 1; r <= bb[i]; ++r) g_row_off[r] = k4 + i;
            prev = bb[i];
        }
        if (k4 + 4 == nnz) {
            for (int r = bb[3] + 1; r <= N; ++r) g_row_off[r] = nnz;
        }
    } else {
        int prev = (k4 == 0) ? -1 : bidx[k4 - 1];
        for (int i = 0; i < 4 && k4 + i < nnz; ++i) {
            int k = k4 + i;
            g_pairs[k] = make_int2(ftab[aidx[k]], __float_as_int(vals[k]));
            int b = bidx[k];
            for (int r = prev + 1; r <= b; ++r) g_row_off[r] = k;
            prev = b;
            if (k == nnz - 1)
                for (int r = b + 1; r <= N; ++r) g_row_off[r] = nnz;
        }
    }
}

__global__ void convert_w_kernel(const float* __restrict__ W, int n) {
    int k = blockIdx.x * blockDim.x + threadIdx.x;   // half2 index
    if (2 * k + 1 < n) {
        float2 f = *(const float2*)(W + 2 * k);
        ((__half2*)g_whalf)[k] = __float22half2_rn(f);
    }
}

// One nnz: one LDS.64 of 4 fp16 cols, fp32 accumulate via packed fma.rn.f32x2.
__device__ __forceinline__ void accum1(int col, int vbits, const char* Wsl,
                                       ull& a0, ull& a1) {
    uint2 u = *(const uint2*)(Wsl + col * (SLICE * 2));
    float2 f0 = __half22float2(*(__half2*)&u.x);
    float2 f1 = __half22float2(*(__half2*)&u.y);
    ull vv;
    asm("mov.b64 %0, {%1, %1};" : "=l"(vv) : "r"(vbits));
    asm("fma.rn.f32x2 %0, %1, %2, %0;" : "+l"(a0) : "l"(vv), "l"(*(ull*)&f0));
    asm("fma.rn.f32x2 %0, %1, %2, %0;" : "+l"(a1) : "l"(vv), "l"(*(ull*)&f1));
}

__device__ __forceinline__ void row_pairs(const int4* stq, int h,
                                          const char* Wsl, ull& a0, ull& a1) {
#pragma unroll 2
    for (int j = 0; j < h; ++j) {
        int4 q = stq[j];
        accum1(q.x, q.y, Wsl, a0, a1);
        accum1(q.z, q.w, Wsl, a0, a1);
    }
}

// Each CTA owns a 128-wide fp16 weight slice in SMEM. Warps pop row-pairs off
// a per-slice atomic queue (prefetched), stage up to 64 nnz per row per chunk.
__global__ __launch_bounds__(BLOCK_THREADS, 1)
void spmm_kernel(float* __restrict__ out, int N, int inter_dim) {
    extern __shared__ char smem[];
    char* Ws = smem;                                      // [inter_dim][128] half
    int2* stage = (int2*)(smem + inter_dim * SLICE * 2);  // [NWARPS][128]

    int slice = blockIdx.x % NSLICES;
    int warp = threadIdx.x >> 5;
    int lane = threadIdx.x & 31;
    int2* st = stage + warp * 128;                        // row0: 0..63, row1: 64..127
    const char* Wsl = Ws + lane * 8;
    int col0 = slice * SLICE;

    // Fill weight slice (16 uint4 per row = 256 B).
    {
        const uint4* Wh4 = (const uint4*)g_whalf;
        int rowv = OUT_COLS / 8;
        int base = col0 / 8;
        int nvec = inter_dim * (SLICE / 8);
        for (int i = threadIdx.x; i < nvec; i += BLOCK_THREADS) {
            int r = i >> 4;
            int c = i & 15;
            ((uint4*)Ws)[r * 16 + c] = Wh4[r * rowv + base + c];
        }
    }
    __syncthreads();

    int npairs = N >> 1;
    int nxt;
    if (lane == 0) nxt = atomicAdd(&g_ctr[slice], 1);
    nxt = __shfl_sync(0xffffffff, nxt, 0);

    while (nxt < npairs) {
        int cur = nxt;
        if (lane == 0) nxt = atomicAdd(&g_ctr[slice], 1);   // prefetch next
        nxt = __shfl_sync(0xffffffff, nxt, 0);

        int row0 = cur * 2, row1 = cur * 2 + 1;
        int s0 = g_row_off[row0], e0 = g_row_off[row0 + 1];
        int s1 = g_row_off[row1], e1 = g_row_off[row1 + 1];
        ull a00 = 0, a01 = 0, a10 = 0, a11 = 0;

        while (s0 < e0 || s1 < e1) {
            int cnt0 = min(64, e0 - s0);
            int cnt1 = min(64, e1 - s1);
            if (lane < cnt0)      st[lane]       = g_pairs[s0 + lane];
            if (lane + 32 < cnt0) st[lane + 32]  = g_pairs[s0 + lane + 32];
            if (lane < cnt1)      st[64 + lane]  = g_pairs[s1 + lane];
            if (lane + 32 < cnt1) st[96 + lane]  = g_pairs[s1 + lane + 32];
            __syncwarp();
            int h0 = cnt0 >> 1, h1 = cnt1 >> 1;
            int joint = min(h0, h1);
            const int4* stA = (const int4*)st;
            const int4* stB = (const int4*)(st + 64);
#pragma unroll 2
            for (int j = 0; j < joint; ++j) {            // two independent chains
                int4 q0 = stA[j];
                int4 q1 = stB[j];
                accum1(q0.x, q0.y, Wsl, a00, a01);
                accum1(q1.x, q1.y, Wsl, a10, a11);
                accum1(q0.z, q0.w, Wsl, a00, a01);
                accum1(q1.z, q1.w, Wsl, a10, a11);
            }
            row_pairs(stA + joint, h0 - joint, Wsl, a00, a01);
            if (cnt0 & 1) {
                int2 p = st[cnt0 - 1];
                accum1(p.x, p.y, Wsl, a00, a01);
            }
            row_pairs(stB + joint, h1 - joint, Wsl, a10, a11);
            if (cnt1 & 1) {
                int2 p = st[64 + cnt1 - 1];
                accum1(p.x, p.y, Wsl, a10, a11);
            }
            __syncwarp();
            s0 += cnt0; s1 += cnt1;
        }
        float2 lo, hi;
        lo = *(float2*)&a00; hi = *(float2*)&a01;
        *(float4*)(out + (size_t)row0 * OUT_COLS + col0 + 4 * lane)
            = make_float4(lo.x, lo.y, hi.x, hi.y);
        lo = *(float2*)&a10; hi = *(float2*)&a11;
        *(float4*)(out + (size_t)row1 * OUT_COLS + col0 + 4 * lane)
            = make_float4(lo.x, lo.y, hi.x, hi.y);
    }
}

extern "C" void kernel_launch(void* const* d_in, const int* in_sizes, int n_in,
                              void* d_out, int out_size) {
    const int*   bidx = (const int*)d_in[0];
    const int*   aidx = (const int*)d_in[1];
    const float* vals = (const float*)d_in[2];
    const int*   ftab = (const int*)d_in[3];
    const float* W    = (const float*)d_in[4];

    int nnz       = in_sizes[0];
    int wn        = in_sizes[4];              // 768*256
    int inter_dim = wn / OUT_COLS;            // 768
    int N         = out_size / OUT_COLS;      // 16384

    size_t smem_bytes = (size_t)inter_dim * SLICE * 2
                      + (size_t)NWARPS * 128 * sizeof(int2);  // 196608 + 32768
    cudaFuncSetAttribute(spmm_kernel,
                         cudaFuncAttributeMaxDynamicSharedMemorySize,
                         (int)smem_bytes);

    prep_kernel<<<(nnz / 4 + 255) / 256, 256>>>(bidx, aidx, vals, ftab, nnz, N);
    convert_w_kernel<<<(wn / 2 + 255) / 256, 256>>>(W, wn);
    spmm_kernel<<<NSLICES * ROW_BLOCKS, BLOCK_THREADS, smem_bytes>>>(
        (float*)d_out, N, inter_dim);
}

// round 13
// speedup vs baseline: 1.1910x; 1.1910x over previous
#include <cuda_runtime.h>
#include <cuda_fp16.h>

#define OUT_COLS 256
#define SLICE 128
#define NSLICES (OUT_COLS / SLICE)          // 2
#define BLOCK_THREADS 1024
#define NWARPS (BLOCK_THREADS / 32)
#define ROW_BLOCKS 76                       // 2 slices * 76 = 152 CTAs = 1 wave

typedef unsigned long long ull;

// scratch (static __device__ globals: no allocations allowed)
__device__ int2   g_pairs[1 << 20];          // (col, val_bits) per nnz
__device__ int    g_row_off[(1 << 16) + 2];  // N+1 row segment offsets
__device__ __half g_whalf[1 << 18];          // fp16 copy of W

// Fused prep + weight conversion. First convBlocks blocks convert W to fp16;
// remaining blocks do the R10 prep (1 nnz/thread: gather + boundary fill).
__global__ void prep_kernel(const int* __restrict__ bidx,
                            const int* __restrict__ aidx,
                            const float* __restrict__ vals,
                            const int* __restrict__ ftab,
                            const float* __restrict__ W,
                            int wn, int convBlocks, int nnz, int N) {
    if ((int)blockIdx.x < convBlocks) {
        int k = blockIdx.x * blockDim.x + threadIdx.x;   // half2 index
        if (2 * k + 1 < wn) {
            float2 f = *(const float2*)(W + 2 * k);
            ((__half2*)g_whalf)[k] = __float22half2_rn(f);
        }
        return;
    }
    int k = (blockIdx.x - convBlocks) * blockDim.x + threadIdx.x;
    if (k >= nnz) return;
    int col = ftab[aidx[k]];
    g_pairs[k] = make_int2(col, __float_as_int(vals[k]));
    int b = bidx[k];
    int prev = (k == 0) ? -1 : bidx[k - 1];
    for (int r = prev + 1; r <= b; ++r) g_row_off[r] = k;
    if (k == nnz - 1) {
        for (int r = b + 1; r <= N; ++r) g_row_off[r] = nnz;
    }
}

// One nnz: one LDS.64 of 4 fp16 cols, fp32 accumulate via packed fma.rn.f32x2.
__device__ __forceinline__ void accum1(int col, int vbits, const char* Wsl,
                                       ull& a0, ull& a1) {
    uint2 u = *(const uint2*)(Wsl + col * (SLICE * 2));
    float2 f0 = __half22float2(*(__half2*)&u.x);
    float2 f1 = __half22float2(*(__half2*)&u.y);
    ull vv;
    asm("mov.b64 %0, {%1, %1};" : "=l"(vv) : "r"(vbits));
    asm("fma.rn.f32x2 %0, %1, %2, %0;" : "+l"(a0) : "l"(vv), "l"(*(ull*)&f0));
    asm("fma.rn.f32x2 %0, %1, %2, %0;" : "+l"(a1) : "l"(vv), "l"(*(ull*)&f1));
}

__device__ __forceinline__ void row_pairs(const int4* stq, int h,
                                          const char* Wsl, ull& a0, ull& a1) {
#pragma unroll 2
    for (int j = 0; j < h; ++j) {
        int4 q = stq[j];
        accum1(q.x, q.y, Wsl, a0, a1);
        accum1(q.z, q.w, Wsl, a0, a1);
    }
}

// Each CTA owns a 128-wide fp16 weight slice in SMEM and a contiguous range of
// row-pairs; warps pop pairs off a per-CTA SMEM counter (prefetched one ahead).
__global__ __launch_bounds__(BLOCK_THREADS, 1)
void spmm_kernel(float* __restrict__ out, int N, int inter_dim) {
    extern __shared__ char smem[];
    char* Ws = smem;                                      // [inter_dim][128] half
    int2* stage = (int2*)(smem + inter_dim * SLICE * 2);  // [NWARPS][64]
    int* ctr = (int*)(stage + NWARPS * 64);               // CTA work counter

    int slice = blockIdx.x % NSLICES;
    int rb    = blockIdx.x / NSLICES;

    int warp = threadIdx.x >> 5;
    int lane = threadIdx.x & 31;
    int2* st = stage + warp * 64;
    const int4* stA = (const int4*)st;
    const int4* stB = (const int4*)(st + 32);
    const char* Wsl = Ws + lane * 8;
    int col0 = slice * SLICE;

    int P = N >> 1;                                       // total row-pairs
    int pair_lo = (int)(((long long)rb * P) / ROW_BLOCKS);
    int pair_hi = (int)(((long long)(rb + 1) * P) / ROW_BLOCKS);
    if (threadIdx.x == 0) *ctr = pair_lo;

    // Fill weight slice (16 uint4 per row = 256 B).
    {
        const uint4* Wh4 = (const uint4*)g_whalf;
        int rowv = OUT_COLS / 8;
        int base = col0 / 8;
        int nvec = inter_dim * (SLICE / 8);
        for (int i = threadIdx.x; i < nvec; i += BLOCK_THREADS) {
            int r = i >> 4;
            int c = i & 15;
            ((uint4*)Ws)[r * 16 + c] = Wh4[r * rowv + base + c];
        }
    }
    __syncthreads();

    int nxt;
    if (lane == 0) nxt = atomicAdd(ctr, 1);
    nxt = __shfl_sync(0xffffffff, nxt, 0);

    while (nxt < pair_hi) {
        int cur = nxt;
        if (lane == 0) nxt = atomicAdd(ctr, 1);           // prefetch next pop
        nxt = __shfl_sync(0xffffffff, nxt, 0);

        int row0 = cur * 2, row1 = cur * 2 + 1;           // N even
        int s0 = g_row_off[row0], e0 = g_row_off[row0 + 1];
        int s1 = g_row_off[row1], e1 = g_row_off[row1 + 1];
        ull a00 = 0, a01 = 0, a10 = 0, a11 = 0;

        while (s0 < e0 || s1 < e1) {
            int cnt0 = min(32, e0 - s0);
            int cnt1 = min(32, e1 - s1);
            if (lane < cnt0) st[lane]      = g_pairs[s0 + lane];
            if (lane < cnt1) st[32 + lane] = g_pairs[s1 + lane];
            __syncwarp();
            int h0 = cnt0 >> 1, h1 = cnt1 >> 1;
            int joint = min(h0, h1);
#pragma unroll 2
            for (int j = 0; j < joint; ++j) {             // two independent chains
                int4 q0 = stA[j];
                int4 q1 = stB[j];
                accum1(q0.x, q0.y, Wsl, a00, a01);
                accum1(q1.x, q1.y, Wsl, a10, a11);
                accum1(q0.z, q0.w, Wsl, a00, a01);
                accum1(q1.z, q1.w, Wsl, a10, a11);
            }
            row_pairs(stA + joint, h0 - joint, Wsl, a00, a01);
            if (cnt0 & 1) {
                int2 p = st[cnt0 - 1];
                accum1(p.x, p.y, Wsl, a00, a01);
            }
            row_pairs(stB + joint, h1 - joint, Wsl, a10, a11);
            if (cnt1 & 1) {
                int2 p = st[32 + cnt1 - 1];
                accum1(p.x, p.y, Wsl, a10, a11);
            }
            __syncwarp();
            s0 += cnt0; s1 += cnt1;
        }
        float2 lo, hi;
        lo = *(float2*)&a00; hi = *(float2*)&a01;
        *(float4*)(out + (size_t)row0 * OUT_COLS + col0 + 4 * lane)
            = make_float4(lo.x, lo.y, hi.x, hi.y);
        lo = *(float2*)&a10; hi = *(float2*)&a11;
        *(float4*)(out + (size_t)row1 * OUT_COLS + col0 + 4 * lane)
            = make_float4(lo.x, lo.y, hi.x, hi.y);
    }
}

extern "C" void kernel_launch(void* const* d_in, const int* in_sizes, int n_in,
                              void* d_out, int out_size) {
    const int*   bidx = (const int*)d_in[0];
    const int*   aidx = (const int*)d_in[1];
    const float* vals = (const float*)d_in[2];
    const int*   ftab = (const int*)d_in[3];
    const float* W    = (const float*)d_in[4];

    int nnz       = in_sizes[0];
    int wn        = in_sizes[4];              // 768*256
    int inter_dim = wn / OUT_COLS;            // 768
    int N         = out_size / OUT_COLS;      // 16384

    size_t smem_bytes = (size_t)inter_dim * SLICE * 2
                      + (size_t)NWARPS * 64 * sizeof(int2) + 128;
    cudaFuncSetAttribute(spmm_kernel,
                         cudaFuncAttributeMaxDynamicSharedMemorySize,
                         (int)smem_bytes);

    int convBlocks = (wn / 2 + 255) / 256;                 // 384
    int prepBlocks = (nnz + 255) / 256;                    // 2048
    prep_kernel<<<convBlocks + prepBlocks, 256>>>(bidx, aidx, vals, ftab,
                                                  W, wn, convBlocks, nnz, N);
    spmm_kernel<<<NSLICES * ROW_BLOCKS, BLOCK_THREADS, smem_bytes>>>(
        (float*)d_out, N, inter_dim);
}

// round 14
// speedup vs baseline: 1.7029x; 1.4298x over previous
#include <cuda_runtime.h>
#include <cuda_fp16.h>

#define OUT_COLS 256
#define SLICE 128
#define NSLICES (OUT_COLS / SLICE)          // 2
#define BLOCK_THREADS 1024
#define NWARPS (BLOCK_THREADS / 32)
#define ROW_BLOCKS 76                       // 2 slices * 76 = 152 CTAs = 1 wave

typedef unsigned long long ull;

// scratch (static __device__ globals: no allocations allowed)
__device__ int2   g_pairs[1 << 20];          // (col, val_bits) per nnz
__device__ int    g_row_off[(1 << 16) + 2];  // N+1 row segment offsets
__device__ __half g_whalf[1 << 18];          // fp16 copy of W

// Fused prep + weight conversion. First convBlocks blocks convert W to fp16;
// remaining blocks do the prep (1 nnz/thread: gather + boundary fill).
__global__ void prep_kernel(const int* __restrict__ bidx,
                            const int* __restrict__ aidx,
                            const float* __restrict__ vals,
                            const int* __restrict__ ftab,
                            const float* __restrict__ W,
                            int wn, int convBlocks, int nnz, int N) {
    if ((int)blockIdx.x < convBlocks) {
        int k = blockIdx.x * blockDim.x + threadIdx.x;   // half2 index
        if (2 * k + 1 < wn) {
            float2 f = *(const float2*)(W + 2 * k);
            ((__half2*)g_whalf)[k] = __float22half2_rn(f);
        }
        return;
    }
    int k = (blockIdx.x - convBlocks) * blockDim.x + threadIdx.x;
    if (k >= nnz) return;
    int col = ftab[aidx[k]];
    g_pairs[k] = make_int2(col, __float_as_int(vals[k]));
    int b = bidx[k];
    int prev = (k == 0) ? -1 : bidx[k - 1];
    for (int r = prev + 1; r <= b; ++r) g_row_off[r] = k;
    if (k == nnz - 1) {
        for (int r = b + 1; r <= N; ++r) g_row_off[r] = nnz;
    }
}

// One nnz: one LDS.64 of 4 fp16 cols, fp32 accumulate via packed fma.rn.f32x2.
__device__ __forceinline__ void accum1(int col, int vbits, const char* Wsl,
                                       ull& a0, ull& a1) {
    uint2 u = *(const uint2*)(Wsl + col * (SLICE * 2));
    float2 f0 = __half22float2(*(__half2*)&u.x);
    float2 f1 = __half22float2(*(__half2*)&u.y);
    ull vv;
    asm("mov.b64 %0, {%1, %1};" : "=l"(vv) : "r"(vbits));
    asm("fma.rn.f32x2 %0, %1, %2, %0;" : "+l"(a0) : "l"(vv), "l"(*(ull*)&f0));
    asm("fma.rn.f32x2 %0, %1, %2, %0;" : "+l"(a1) : "l"(vv), "l"(*(ull*)&f1));
}

__device__ __forceinline__ void row_pairs(const int4* stq, int h,
                                          const char* Wsl, ull& a0, ull& a1) {
#pragma unroll 2
    for (int j = 0; j < h; ++j) {
        int4 q = stq[j];
        accum1(q.x, q.y, Wsl, a0, a1);
        accum1(q.z, q.w, Wsl, a0, a1);
    }
}

// Each CTA owns a 128-wide fp16 weight slice in SMEM. Each warp processes two
// adjacent rows concurrently (two independent LDS->cvt->FFMA2 chains), with a
// static strided schedule (R10 known-good structure).
__global__ __launch_bounds__(BLOCK_THREADS, 1)
void spmm_kernel(float* __restrict__ out, int N, int inter_dim) {
    extern __shared__ char smem[];
    char* Ws = smem;                                      // [inter_dim][128] half
    int2* stage = (int2*)(smem + inter_dim * SLICE * 2);  // [NWARPS][64]

    int slice = blockIdx.x % NSLICES;
    int rb    = blockIdx.x / NSLICES;
    int nrb   = gridDim.x / NSLICES;

    int warp = threadIdx.x >> 5;
    int lane = threadIdx.x & 31;
    int2* st = stage + warp * 64;
    const int4* stA = (const int4*)st;
    const int4* stB = (const int4*)(st + 32);
    const char* Wsl = Ws + lane * 8;                      // this lane's 4 cols
    int col0 = slice * SLICE;

    // Fill weight slice (16 uint4 per row = 256 B).
    {
        const uint4* Wh4 = (const uint4*)g_whalf;
        int rowv = OUT_COLS / 8;
        int base = col0 / 8;
        int nvec = inter_dim * (SLICE / 8);
        for (int i = threadIdx.x; i < nvec; i += BLOCK_THREADS) {
            int r = i >> 4;
            int c = i & 15;
            ((uint4*)Ws)[r * 16 + c] = Wh4[r * rowv + base + c];
        }
    }
    __syncthreads();

    int rowStride = nrb * NWARPS * 2;
    for (int row0 = (rb * NWARPS + warp) * 2; row0 < N; row0 += rowStride) {
        int row1 = row0 + 1;                              // N even
        int s0 = g_row_off[row0], e0 = g_row_off[row0 + 1];
        int s1 = g_row_off[row1], e1 = g_row_off[row1 + 1];
        ull a00 = 0, a01 = 0, a10 = 0, a11 = 0;

        while (s0 < e0 || s1 < e1) {
            int cnt0 = min(32, e0 - s0);
            int cnt1 = min(32, e1 - s1);
            if (lane < cnt0) st[lane]      = g_pairs[s0 + lane];
            if (lane < cnt1) st[32 + lane] = g_pairs[s1 + lane];
            __syncwarp();
            int h0 = cnt0 >> 1, h1 = cnt1 >> 1;
            int joint = min(h0, h1);
#pragma unroll 2
            for (int j = 0; j < joint; ++j) {             // two independent chains
                int4 q0 = stA[j];
                int4 q1 = stB[j];
                accum1(q0.x, q0.y, Wsl, a00, a01);
                accum1(q1.x, q1.y, Wsl, a10, a11);
                accum1(q0.z, q0.w, Wsl, a00, a01);
                accum1(q1.z, q1.w, Wsl, a10, a11);
            }
            row_pairs(stA + joint, h0 - joint, Wsl, a00, a01);
            if (cnt0 & 1) {
                int2 p = st[cnt0 - 1];
                accum1(p.x, p.y, Wsl, a00, a01);
            }
            row_pairs(stB + joint, h1 - joint, Wsl, a10, a11);
            if (cnt1 & 1) {
                int2 p = st[32 + cnt1 - 1];
                accum1(p.x, p.y, Wsl, a10, a11);
            }
            __syncwarp();
            s0 += cnt0; s1 += cnt1;
        }
        float2 lo, hi;
        lo = *(float2*)&a00; hi = *(float2*)&a01;
        *(float4*)(out + (size_t)row0 * OUT_COLS + col0 + 4 * lane)
            = make_float4(lo.x, lo.y, hi.x, hi.y);
        lo = *(float2*)&a10; hi = *(float2*)&a11;
        *(float4*)(out + (size_t)row1 * OUT_COLS + col0 + 4 * lane)
            = make_float4(lo.x, lo.y, hi.x, hi.y);
    }
}

extern "C" void kernel_launch(void* const* d_in, const int* in_sizes, int n_in,
                              void* d_out, int out_size) {
    const int*   bidx = (const int*)d_in[0];
    const int*   aidx = (const int*)d_in[1];
    const float* vals = (const float*)d_in[2];
    const int*   ftab = (const int*)d_in[3];
    const float* W    = (const float*)d_in[4];

    int nnz       = in_sizes[0];
    int wn        = in_sizes[4];              // 768*256
    int inter_dim = wn / OUT_COLS;            // 768
    int N         = out_size / OUT_COLS;      // 16384

    size_t smem_bytes = (size_t)inter_dim * SLICE * 2
                      + (size_t)NWARPS * 64 * sizeof(int2);   // 196608 + 16384
    cudaFuncSetAttribute(spmm_kernel,
                         cudaFuncAttributeMaxDynamicSharedMemorySize,
                         (int)smem_bytes);

    int convBlocks = (wn / 2 + 255) / 256;                 // 384
    int prepBlocks = (nnz + 255) / 256;                    // 2048
    prep_kernel<<<convBlocks + prepBlocks, 256>>>(bidx, aidx, vals, ftab,
                                                  W, wn, convBlocks, nnz, N);
    spmm_kernel<<<NSLICES * ROW_BLOCKS, BLOCK_THREADS, smem_bytes>>>(
        (float*)d_out, N, inter_dim);
}